// round 4
// baseline (speedup 1.0000x reference)
#include <cuda_runtime.h>
#include <cstdint>

// ============================================================================
// ProteinSpatioTemporalAttention — round 4:
//  - tf32 mma.sync GEMMs (cp.async double-buffered), QKV merged launch
//  - gate GEMM K reduced 1024->640 via precomputed Beff = [W1 | W2 @ Vexp]
//  - vproj via smem-staged V (16 tokens/block)
//  - RoPE via precomputed cos/sin table (no transcendentals in hot path)
// ============================================================================

namespace {
constexpr int B_  = 4;
constexpr int T_  = 64;
constexpr int L_  = 256;
constexpr int C_  = 512;
constexpr int HD_ = 64;
constexpr int RK_ = 128;
constexpr int N_  = B_ * T_ * L_;   // 65536 tokens

constexpr int PAD_ = 36;            // smem row stride (floats), conflict-free
constexpr int GEMM_SMEM = 2 * 2 * 128 * PAD_ * 4;   // 73728 bytes
}

// -------------------- scratch (device globals; no cudaMalloc) ---------------
__device__ float g_xn [N_ * C_];
__device__ float g_q  [N_ * C_];
__device__ float g_k  [N_ * C_];
__device__ float g_y  [N_ * C_];
__device__ float g_x1 [N_ * C_];
__device__ float g_x2 [N_ * C_];
__device__ float g_qlo[N_ * RK_];
__device__ float g_klo[N_ * RK_];
__device__ float g_vlo[N_ * RK_];
__device__ float g_olo[N_ * RK_];
__device__ float g_befft[512 * 640];
__device__ float g_beffa[512 * 640];
__device__ float g_ropec[256 * 32];
__device__ float g_ropes[256 * 32];

// ============================ PTX helpers ===================================
__device__ __forceinline__ uint32_t smem_u32(const void* p) {
    uint32_t a;
    asm("{ .reg .u64 t; cvta.to.shared.u64 t, %1; cvt.u32.u64 %0, t; }"
        : "=r"(a) : "l"(p));
    return a;
}
__device__ __forceinline__ uint32_t f2tf(float x) {
    uint32_t r;
    asm("cvt.rna.tf32.f32 %0, %1;" : "=r"(r) : "f"(x));
    return r;
}
__device__ __forceinline__ void mma_tf32(float* c, const uint32_t* a, const uint32_t* b) {
    asm volatile("mma.sync.aligned.m16n8k8.row.col.f32.tf32.tf32.f32 "
        "{%0,%1,%2,%3}, {%4,%5,%6,%7}, {%8,%9}, {%0,%1,%2,%3};"
        : "+f"(c[0]), "+f"(c[1]), "+f"(c[2]), "+f"(c[3])
        : "r"(a[0]), "r"(a[1]), "r"(a[2]), "r"(a[3]), "r"(b[0]), "r"(b[1]));
}
#define CP_ASYNC16(dst, src) \
    asm volatile("cp.async.cg.shared.global [%0], [%1], 16;" :: "r"(dst), "l"(src))
#define CP_COMMIT() asm volatile("cp.async.commit_group;" ::: "memory")
#define CP_WAIT1()  asm volatile("cp.async.wait_group 1;" ::: "memory")
#define CP_WAIT0()  asm volatile("cp.async.wait_group 0;" ::: "memory")

// ============================ tf32 mma GEMM body ============================
// C[m,n] = sum_k A[m,k]*B[n,k]; A virtual concat [A0(K1,lda0) | A1(K2,lda1)].
// B row stride = Kw. mode 0: store; 1: gate-combine; 2: +bias +resid.
__device__ __forceinline__
void gemm_body(const float* __restrict__ A0, int lda0,
               const float* __restrict__ A1, int lda1,
               const float* __restrict__ Bw,
               const float* __restrict__ bias,
               const float* __restrict__ resid,
               const float* __restrict__ yv,
               float* __restrict__ C, int ldc,
               int K1, int Kw, int mode, int m0, int n0)
{
    extern __shared__ float sm[];
    float* As = sm;                        // [2][128*PAD_]
    float* Bs = sm + 2 * 128 * PAD_;       // [2][128*PAD_]

    const int tid  = threadIdx.x;
    const int lane = tid & 31;
    const int wid  = tid >> 5;
    const int NC   = Kw >> 5;
    const int NC1  = K1 >> 5;

    const int lr = tid >> 3;            // 0..31
    const int lk = (tid & 7) * 4;       // 0,4,...,28

    const uint32_t aS0 = smem_u32(As);
    const uint32_t bS0 = smem_u32(Bs);

    auto prefetch = [&](int c, int s) {
        const float* Ap; int kb, lda;
        if (c < NC1) { Ap = A0; lda = lda0; kb = c * 32; }
        else         { Ap = A1; lda = lda1; kb = (c - NC1) * 32; }
        const uint32_t aT = aS0 + (uint32_t)(s * 128 * PAD_) * 4;
        const uint32_t bT = bS0 + (uint32_t)(s * 128 * PAD_) * 4;
        const float* srcB = Bw + (size_t)n0 * Kw + c * 32;
        #pragma unroll
        for (int it = 0; it < 4; ++it) {
            const int r = lr + it * 32;
            CP_ASYNC16(aT + (uint32_t)(r * PAD_ + lk) * 4,
                       Ap + (size_t)(m0 + r) * lda + kb + lk);
            CP_ASYNC16(bT + (uint32_t)(r * PAD_ + lk) * 4,
                       srcB + (size_t)r * Kw + lk);
        }
    };

    const int wm = (wid & 1) * 64;
    const int wn = (wid >> 1) * 32;

    float acc[4][4][4];
    #pragma unroll
    for (int i = 0; i < 4; ++i)
        #pragma unroll
        for (int j = 0; j < 4; ++j)
            #pragma unroll
            for (int r = 0; r < 4; ++r) acc[i][j][r] = 0.f;

    prefetch(0, 0);
    CP_COMMIT();

    for (int c = 0; c < NC; ++c) {
        const int s = c & 1;
        if (c + 1 < NC) { prefetch(c + 1, s ^ 1); CP_COMMIT(); CP_WAIT1(); }
        else            { CP_WAIT0(); }
        __syncthreads();

        const float* a_s = As + s * 128 * PAD_ + (wm + (lane >> 2)) * PAD_ + (lane & 3);
        const float* b_s = Bs + s * 128 * PAD_ + (wn + (lane >> 2)) * PAD_ + (lane & 3);

        #pragma unroll
        for (int ks = 0; ks < 4; ++ks) {
            const int k0 = ks * 8;
            uint32_t af[4][4];
            #pragma unroll
            for (int i = 0; i < 4; ++i) {
                const float* ap = a_s + i * 16 * PAD_ + k0;
                af[i][0] = f2tf(ap[0]);
                af[i][1] = f2tf(ap[8 * PAD_]);
                af[i][2] = f2tf(ap[4]);
                af[i][3] = f2tf(ap[8 * PAD_ + 4]);
            }
            #pragma unroll
            for (int j = 0; j < 4; ++j) {
                const float* bp = b_s + j * 8 * PAD_ + k0;
                uint32_t bf[2] = { f2tf(bp[0]), f2tf(bp[4]) };
                #pragma unroll
                for (int i = 0; i < 4; ++i) mma_tf32(acc[i][j], af[i], bf);
            }
        }
        __syncthreads();
    }

    // ---------------- epilogue ----------------
    const int row0 = m0 + wm + (lane >> 2);
    const int col0 = n0 + wn + (lane & 3) * 2;

    #pragma unroll
    for (int i = 0; i < 4; ++i) {
        #pragma unroll
        for (int half = 0; half < 2; ++half) {
            const int r = row0 + i * 16 + half * 8;
            float*       crow = C + (size_t)r * ldc;
            const float* rrow = resid ? resid + (size_t)r * ldc : nullptr;
            const float* yrow = yv    ? yv    + (size_t)r * ldc : nullptr;
            #pragma unroll
            for (int j = 0; j < 4; ++j) {
                const int cc = col0 + j * 8;
                float v0 = acc[i][j][half * 2 + 0];
                float v1 = acc[i][j][half * 2 + 1];
                if (mode == 0) {
                    *(float2*)(crow + cc) = make_float2(v0, v1);
                } else if (mode == 1) {
                    float2 bi = *(const float2*)(bias + cc);
                    float2 rv = *(const float2*)(rrow + cc);
                    float2 yw = *(const float2*)(yrow + cc);
                    float g0 = 1.f / (1.f + __expf(-(v0 + bi.x)));
                    float g1 = 1.f / (1.f + __expf(-(v1 + bi.y)));
                    *(float2*)(crow + cc) = make_float2(
                        g0 * rv.x + (1.f - g0) * yw.x,
                        g1 * rv.y + (1.f - g1) * yw.y);
                } else {
                    float2 bi = *(const float2*)(bias + cc);
                    float2 rv = *(const float2*)(rrow + cc);
                    *(float2*)(crow + cc) = make_float2(v0 + bi.x + rv.x,
                                                        v1 + bi.y + rv.y);
                }
            }
        }
    }
}

// QKV: one launch, qkv index fastest for L2 A-tile reuse. N=128 each.
__global__ __launch_bounds__(256, 2)
void gemm_qkv(const float* __restrict__ A,
              const float* __restrict__ Wq, const float* __restrict__ Wk,
              const float* __restrict__ Wv,
              float* __restrict__ q, float* __restrict__ k, float* __restrict__ v)
{
    const int bx  = blockIdx.x;
    const int sel = bx % 3;
    const int m0  = (bx / 3) * 128;
    const float* Bw = (sel == 0) ? Wq : (sel == 1) ? Wk : Wv;
    float*       C  = (sel == 0) ? q  : (sel == 1) ? k  : v;
    gemm_body(A, 512, A, 512, Bw, nullptr, nullptr, nullptr, C, 128,
              512, 512, 0, m0, 0);
}

// General GEMM with N=512 (4 n-blocks, n fastest for L2 A reuse).
__global__ __launch_bounds__(256, 2)
void gemm_gen(const float* __restrict__ A0, int lda0,
              const float* __restrict__ A1, int lda1,
              const float* __restrict__ Bw,
              const float* __restrict__ bias,
              const float* __restrict__ resid,
              const float* __restrict__ yv,
              float* __restrict__ C, int K1, int Kw, int mode)
{
    const int bx = blockIdx.x;
    const int m0 = (bx >> 2) * 128;
    const int n0 = (bx & 3) * 128;
    gemm_body(A0, lda0, A1, lda1, Bw, bias, resid, yv, C, 512,
              K1, Kw, mode, m0, n0);
}

// ============================ prep kernels ==================================
// Beff[n, 0:512] = gW[n, 0:512];  Beff[n, 512+j] = sum_d gW[n,512+h*64+d]*V[(h*16+r)*64+d]
__global__ void build_beff(const float* __restrict__ gW,
                           const float* __restrict__ V,
                           float* __restrict__ Beff)
{
    const int n = blockIdx.x;          // 512
    const int tid = threadIdx.x;       // 128
    ((float4*)(Beff + (size_t)n * 640))[tid] =
        ((const float4*)(gW + (size_t)n * 1024))[tid];
    const int h = tid >> 4, r = tid & 15;
    const float* w2 = gW + (size_t)n * 1024 + 512 + h * 64;
    const float* vr = V + (size_t)(h * 16 + r) * 64;
    float s = 0.f;
    #pragma unroll
    for (int d = 0; d < 64; ++d) s = fmaf(w2[d], vr[d], s);
    Beff[(size_t)n * 640 + 512 + tid] = s;
}

__global__ void build_rope(float* __restrict__ rc, float* __restrict__ rs)
{
    const int idx = blockIdx.x * 256 + threadIdx.x;   // 8192 entries
    const int pos = idx >> 5;
    const int ih  = idx & 31;
    const float theta = expf((float)ih * -0.28782313662425572f);  // -ln(10000)/32
    float sn, cs;
    sincosf((float)pos * theta, &sn, &cs);
    rc[idx] = cs;  rs[idx] = sn;
}

// ============================ LayerNorm =====================================
__global__ void ln_kernel(const float* __restrict__ x,
                          const float* __restrict__ g,
                          const float* __restrict__ b,
                          float* __restrict__ out)
{
    const int n   = blockIdx.x;
    const int tid = threadIdx.x;
    const float* xr = x + (size_t)n * C_;

    float v0 = xr[tid];
    float v1 = xr[tid + 256];
    float s = v0 + v1;
    float q = v0 * v0 + v1 * v1;
    #pragma unroll
    for (int o = 16; o; o >>= 1) {
        s += __shfl_xor_sync(0xffffffffu, s, o);
        q += __shfl_xor_sync(0xffffffffu, q, o);
    }
    __shared__ float rs[8], rq[8];
    if ((tid & 31) == 0) { rs[tid >> 5] = s; rq[tid >> 5] = q; }
    __syncthreads();
    float st = 0.f, qt = 0.f;
    #pragma unroll
    for (int w = 0; w < 8; ++w) { st += rs[w]; qt += rq[w]; }

    const float mean = st * (1.f / 512.f);
    const float var  = qt * (1.f / 512.f) - mean * mean;
    const float rstd = rsqrtf(var + 1e-12f);

    float* orow = out + (size_t)n * C_;
    orow[tid]       = (v0 - mean) * rstd * g[tid]       + b[tid];
    orow[tid + 256] = (v1 - mean) * rstd * g[tid + 256] + b[tid + 256];
}

// ====================== rank->head expansion + RoPE (table) =================
__global__ void expand_rope_kernel(const float* __restrict__ ql,
                                   const float* __restrict__ kl,
                                   const float* __restrict__ U,
                                   const float* __restrict__ rc,
                                   const float* __restrict__ rs,
                                   float* __restrict__ q,
                                   float* __restrict__ k,
                                   int timeMode)
{
    const int n = blockIdx.x;
    const int tid = threadIdx.x;
    __shared__ float sq[128], sk[128];
    sq[tid] = ql[(size_t)n * RK_ + tid];
    sk[tid] = kl[(size_t)n * RK_ + tid];
    __syncthreads();

    const int pos = timeMode ? ((n >> 8) & 63) : (n & 255);

    #pragma unroll
    for (int pp = 0; pp < 2; ++pp) {
        const int p  = tid + pp * 128;
        const int h  = p >> 5;
        const int ih = p & 31;
        const float* Ue = U + (size_t)(h * 64 + 2 * ih) * 16;
        const float* Uo = Ue + 16;
        const float* sqh = sq + h * 16;
        const float* skh = sk + h * 16;

        float qe = 0.f, qo = 0.f, ke = 0.f, ko = 0.f;
        #pragma unroll
        for (int r = 0; r < 16; ++r) {
            const float ue = __ldg(Ue + r);
            const float uo = __ldg(Uo + r);
            qe = fmaf(ue, sqh[r], qe);  qo = fmaf(uo, sqh[r], qo);
            ke = fmaf(ue, skh[r], ke);  ko = fmaf(uo, skh[r], ko);
        }
        const float cs = __ldg(rc + pos * 32 + ih);
        const float sn = __ldg(rs + pos * 32 + ih);

        const size_t base = (size_t)n * C_ + h * 64 + 2 * ih;
        q[base]     = qe * cs - qo * sn;
        q[base + 1] = qe * sn + qo * cs;
        k[base]     = ke * cs - ko * sn;
        k[base + 1] = ke * sn + ko * cs;
    }
}

// ============================ Attention =====================================
template <int KV_TILES, bool TIME>
__global__ __launch_bounds__(256)
void attn_kernel(const float* __restrict__ q, const float* __restrict__ k,
                 const float* __restrict__ vlow, float* __restrict__ olow)
{
    __shared__ float qsT[64 * 68];
    __shared__ float kps[64 * 68];
    __shared__ float vs [64 * 16];
    __shared__ float Os [64 * 16];
    __shared__ float mrow[64], lrow[64], arow[64];

    const int tid  = threadIdx.x;
    const int head = blockIdx.y;
    int base, step;
    if (TIME) {
        const int b = blockIdx.x >> 8;
        const int l = blockIdx.x & 255;
        base = b * (T_ * L_) + l;  step = L_;
    } else {
        base = blockIdx.x * L_;    step = 1;
    }
    const int q0 = blockIdx.z * 64;

    #pragma unroll
    for (int p = 0; p < 4; ++p) {
        const int f  = tid + p * 256;
        const int i  = f >> 4;
        const int dq = (f & 15) * 4;
        const int tok = base + (q0 + i) * step;
        float4 v = *(const float4*)(q + (size_t)tok * C_ + head * HD_ + dq);
        qsT[(dq+0)*68 + i] = v.x * 0.125f;
        qsT[(dq+1)*68 + i] = v.y * 0.125f;
        qsT[(dq+2)*68 + i] = v.z * 0.125f;
        qsT[(dq+3)*68 + i] = v.w * 0.125f;
    }
    if (tid < 64) { mrow[tid] = -1e30f; lrow[tid] = 0.f; }
    for (int p = tid; p < 1024; p += 256) Os[p] = 0.f;
    __syncthreads();

    const int ti = tid >> 4, tj = tid & 15;
    const int oi = tid >> 2, orq = (tid & 3) * 4;

    for (int kt = 0; kt < KV_TILES; ++kt) {
        #pragma unroll
        for (int p = 0; p < 4; ++p) {
            const int f  = tid + p * 256;
            const int j  = f >> 4;
            const int dq = (f & 15) * 4;
            const int tok = base + (kt * 64 + j) * step;
            float4 v = *(const float4*)(k + (size_t)tok * C_ + head * HD_ + dq);
            kps[(dq+0)*68 + j] = v.x;
            kps[(dq+1)*68 + j] = v.y;
            kps[(dq+2)*68 + j] = v.z;
            kps[(dq+3)*68 + j] = v.w;
        }
        {
            const int j = tid >> 2, rq = (tid & 3) * 4;
            const int tok = base + (kt * 64 + j) * step;
            *(float4*)&vs[j * 16 + rq] =
                *(const float4*)(vlow + (size_t)tok * RK_ + head * 16 + rq);
        }
        __syncthreads();

        float acc[16];
        #pragma unroll
        for (int z = 0; z < 16; ++z) acc[z] = 0.f;
        #pragma unroll 8
        for (int d = 0; d < 64; ++d) {
            float4 qa = *(const float4*)&qsT[d * 68 + ti * 4];
            float4 kb = *(const float4*)&kps[d * 68 + tj * 4];
            const float qv[4] = {qa.x, qa.y, qa.z, qa.w};
            const float kv[4] = {kb.x, kb.y, kb.z, kb.w};
            #pragma unroll
            for (int a = 0; a < 4; ++a)
                #pragma unroll
                for (int b = 0; b < 4; ++b)
                    acc[a*4+b] = fmaf(qv[a], kv[b], acc[a*4+b]);
        }
        __syncthreads();
        #pragma unroll
        for (int a = 0; a < 4; ++a)
            #pragma unroll
            for (int b = 0; b < 4; ++b)
                kps[(ti*4+a)*68 + tj*4+b] = acc[a*4+b];
        __syncthreads();

        {
            const int wd = tid >> 5, lane = tid & 31;
            #pragma unroll
            for (int rr = 0; rr < 8; ++rr) {
                const int i = wd * 8 + rr;
                float s0 = kps[i*68 + lane];
                float s1 = kps[i*68 + 32 + lane];
                float tm = fmaxf(s0, s1);
                #pragma unroll
                for (int o = 16; o; o >>= 1) tm = fmaxf(tm, __shfl_xor_sync(0xffffffffu, tm, o));
                const float m_old = mrow[i];
                const float m_new = fmaxf(m_old, tm);
                const float p0 = __expf(s0 - m_new);
                const float p1 = __expf(s1 - m_new);
                kps[i*68 + lane] = p0;
                kps[i*68 + 32 + lane] = p1;
                float ts = p0 + p1;
                #pragma unroll
                for (int o = 16; o; o >>= 1) ts += __shfl_xor_sync(0xffffffffu, ts, o);
                if (lane == 0) {
                    const float al = __expf(m_old - m_new);
                    lrow[i] = lrow[i] * al + ts;
                    arow[i] = al;
                    mrow[i] = m_new;
                }
            }
        }
        __syncthreads();

        {
            float4 o = *(float4*)&Os[oi * 16 + orq];
            const float al = arow[oi];
            o.x *= al; o.y *= al; o.z *= al; o.w *= al;
            #pragma unroll 8
            for (int j = 0; j < 64; ++j) {
                const float pv = kps[oi * 68 + j];
                float4 v4 = *(const float4*)&vs[j * 16 + orq];
                o.x = fmaf(pv, v4.x, o.x);
                o.y = fmaf(pv, v4.y, o.y);
                o.z = fmaf(pv, v4.z, o.z);
                o.w = fmaf(pv, v4.w, o.w);
            }
            *(float4*)&Os[oi * 16 + orq] = o;
        }
        __syncthreads();
    }

    {
        const int tok = base + (q0 + oi) * step;
        const float inv = 1.f / lrow[oi];
        float4 o = *(float4*)&Os[oi * 16 + orq];
        o.x *= inv; o.y *= inv; o.z *= inv; o.w *= inv;
        *(float4*)(olow + (size_t)tok * RK_ + head * 16 + orq) = o;
    }
}

// ============================ V projection (smem V, 16 tok/block) ===========
__global__ __launch_bounds__(256)
void vproj16(const float* __restrict__ olow, const float* __restrict__ V,
             float* __restrict__ y)
{
    __shared__ float Vs[8192];        // 8*16*64
    __shared__ float os[16 * 128];

    const int tid = threadIdx.x;
    const int n0  = blockIdx.x * 16;

    #pragma unroll
    for (int i = 0; i < 8; ++i)
        ((float4*)Vs)[tid + i * 256] = ((const float4*)V)[tid + i * 256];
    {
        const float4* src = (const float4*)(olow + (size_t)n0 * RK_);
        ((float4*)os)[tid]       = src[tid];
        ((float4*)os)[tid + 256] = src[tid + 256];
    }
    __syncthreads();

    const int tt = tid >> 4;           // token 0..15
    const int c0 = (tid & 15) * 32;    // output column base
    const int h  = c0 >> 6;
    const int d0 = c0 & 63;
    const float* oh = os + tt * 128 + h * 16;
    const float* vb = Vs + (h * 16) * 64 + d0;

    float acc[32];
    #pragma unroll
    for (int i = 0; i < 32; ++i) acc[i] = 0.f;

    #pragma unroll
    for (int r = 0; r < 16; ++r) {
        const float o = oh[r];
        #pragma unroll
        for (int cc = 0; cc < 8; ++cc) {
            float4 v4 = *(const float4*)(vb + r * 64 + cc * 4);
            acc[cc*4+0] = fmaf(o, v4.x, acc[cc*4+0]);
            acc[cc*4+1] = fmaf(o, v4.y, acc[cc*4+1]);
            acc[cc*4+2] = fmaf(o, v4.z, acc[cc*4+2]);
            acc[cc*4+3] = fmaf(o, v4.w, acc[cc*4+3]);
        }
    }
    float* yrow = y + (size_t)(n0 + tt) * C_ + c0;
    #pragma unroll
    for (int cc = 0; cc < 8; ++cc)
        *(float4*)(yrow + cc * 4) = make_float4(acc[cc*4+0], acc[cc*4+1],
                                                acc[cc*4+2], acc[cc*4+3]);
}

// ============================ launch ========================================
extern "C" void kernel_launch(void* const* d_in, const int* in_sizes, int n_in,
                              void* d_out, int out_size)
{
    const float* x    = (const float*)d_in[0];
    const float* tWq  = (const float*)d_in[3];
    const float* tWk  = (const float*)d_in[4];
    const float* tWv  = (const float*)d_in[5];
    const float* tU   = (const float*)d_in[6];
    const float* tV   = (const float*)d_in[7];
    const float* aWq  = (const float*)d_in[8];
    const float* aWk  = (const float*)d_in[9];
    const float* aWv  = (const float*)d_in[10];
    const float* aU   = (const float*)d_in[11];
    const float* aV   = (const float*)d_in[12];
    const float* ln1g = (const float*)d_in[13];
    const float* ln1b = (const float*)d_in[14];
    const float* ln2g = (const float*)d_in[15];
    const float* ln2b = (const float*)d_in[16];
    const float* ln3g = (const float*)d_in[17];
    const float* ln3b = (const float*)d_in[18];
    const float* projW= (const float*)d_in[19];
    const float* projb= (const float*)d_in[20];
    const float* gtW  = (const float*)d_in[21];
    const float* gtb  = (const float*)d_in[22];
    const float* gaW  = (const float*)d_in[23];
    const float* gab  = (const float*)d_in[24];
    float* out = (float*)d_out;

    float *xn, *qb, *kb, *yb, *x1, *x2, *qlo, *klo, *vlo, *olo;
    float *befft, *beffa, *ropec, *ropes;
    cudaGetSymbolAddress((void**)&xn,  g_xn);
    cudaGetSymbolAddress((void**)&qb,  g_q);
    cudaGetSymbolAddress((void**)&kb,  g_k);
    cudaGetSymbolAddress((void**)&yb,  g_y);
    cudaGetSymbolAddress((void**)&x1,  g_x1);
    cudaGetSymbolAddress((void**)&x2,  g_x2);
    cudaGetSymbolAddress((void**)&qlo, g_qlo);
    cudaGetSymbolAddress((void**)&klo, g_klo);
    cudaGetSymbolAddress((void**)&vlo, g_vlo);
    cudaGetSymbolAddress((void**)&olo, g_olo);
    cudaGetSymbolAddress((void**)&befft, g_befft);
    cudaGetSymbolAddress((void**)&beffa, g_beffa);
    cudaGetSymbolAddress((void**)&ropec, g_ropec);
    cudaGetSymbolAddress((void**)&ropes, g_ropes);

    static bool attr_set = false;
    if (!attr_set) {
        cudaFuncSetAttribute(gemm_qkv, cudaFuncAttributeMaxDynamicSharedMemorySize, GEMM_SMEM);
        cudaFuncSetAttribute(gemm_gen, cudaFuncAttributeMaxDynamicSharedMemorySize, GEMM_SMEM);
        attr_set = true;
    }

    // -------- prep (cheap, deterministic) --------
    build_rope<<<32, 256>>>(ropec, ropes);
    build_beff<<<512, 128>>>(gtW, tV, befft);
    build_beff<<<512, 128>>>(gaW, aV, beffa);

    // ---------------- stage A: time attention ----------------
    ln_kernel<<<N_, 256>>>(x, ln1g, ln1b, xn);
    gemm_qkv<<<3 * (N_ / 128), 256, GEMM_SMEM>>>(xn, tWq, tWk, tWv, qlo, klo, vlo);
    expand_rope_kernel<<<N_, 128>>>(qlo, klo, tU, ropec, ropes, qb, kb, 1);
    attn_kernel<1, true><<<dim3(B_ * L_, 8, 1), 256>>>(qb, kb, vlo, olo);
    vproj16<<<N_ / 16, 256>>>(olo, tV, yb);
    gemm_gen<<<4 * (N_ / 128), 256, GEMM_SMEM>>>(x, 512, olo, 128, befft, gtb, x, yb, x1, 512, 640, 1);

    // ---------------- stage B: residue attention ----------------
    ln_kernel<<<N_, 256>>>(x1, ln2g, ln2b, xn);
    gemm_qkv<<<3 * (N_ / 128), 256, GEMM_SMEM>>>(xn, aWq, aWk, aWv, qlo, klo, vlo);
    expand_rope_kernel<<<N_, 128>>>(qlo, klo, aU, ropec, ropes, qb, kb, 0);
    attn_kernel<4, false><<<dim3(B_ * T_, 8, 4), 256>>>(qb, kb, vlo, olo);
    vproj16<<<N_ / 16, 256>>>(olo, aV, yb);
    gemm_gen<<<4 * (N_ / 128), 256, GEMM_SMEM>>>(x1, 512, olo, 128, beffa, gab, x1, yb, x2, 512, 640, 1);

    // ---------------- stage C: output projection ----------------
    ln_kernel<<<N_, 256>>>(x2, ln3g, ln3b, xn);
    gemm_gen<<<4 * (N_ / 128), 256, GEMM_SMEM>>>(xn, 512, xn, 512, projW, projb, x2, nullptr, out, 512, 512, 2);
}

// round 5
// speedup vs baseline: 1.2955x; 1.2955x over previous
#include <cuda_runtime.h>
#include <cstdint>

// ============================================================================
// ProteinSpatioTemporalAttention — round 5:
//  - tf32 mma.sync GEMMs (cp.async double-buffered), merged QKV, Beff gate
//  - NEW: tf32 mma.sync flash attention (register softmax, shuffled P frags)
//  - vproj reverted to round-3 per-token kernel (round-4 vproj16 had 32-way
//    smem bank conflicts — the cause of the round-4 regression)
// ============================================================================

namespace {
constexpr int B_  = 4;
constexpr int T_  = 64;
constexpr int L_  = 256;
constexpr int C_  = 512;
constexpr int HD_ = 64;
constexpr int RK_ = 128;
constexpr int N_  = B_ * T_ * L_;   // 65536 tokens

constexpr int PAD_ = 36;            // GEMM smem row stride (floats)
constexpr int GEMM_SMEM = 2 * 2 * 128 * PAD_ * 4;   // 73728 bytes
}

// -------------------- scratch (device globals; no cudaMalloc) ---------------
__device__ float g_xn [N_ * C_];
__device__ float g_q  [N_ * C_];
__device__ float g_k  [N_ * C_];
__device__ float g_y  [N_ * C_];
__device__ float g_x1 [N_ * C_];
__device__ float g_x2 [N_ * C_];
__device__ float g_qlo[N_ * RK_];
__device__ float g_klo[N_ * RK_];
__device__ float g_vlo[N_ * RK_];
__device__ float g_olo[N_ * RK_];
__device__ float g_befft[512 * 640];
__device__ float g_beffa[512 * 640];
__device__ float g_ropec[256 * 32];
__device__ float g_ropes[256 * 32];

// ============================ PTX helpers ===================================
__device__ __forceinline__ uint32_t smem_u32(const void* p) {
    uint32_t a;
    asm("{ .reg .u64 t; cvta.to.shared.u64 t, %1; cvt.u32.u64 %0, t; }"
        : "=r"(a) : "l"(p));
    return a;
}
__device__ __forceinline__ uint32_t f2tf(float x) {
    uint32_t r;
    asm("cvt.rna.tf32.f32 %0, %1;" : "=r"(r) : "f"(x));
    return r;
}
__device__ __forceinline__ void mma_tf32(float* c, const uint32_t* a, const uint32_t* b) {
    asm volatile("mma.sync.aligned.m16n8k8.row.col.f32.tf32.tf32.f32 "
        "{%0,%1,%2,%3}, {%4,%5,%6,%7}, {%8,%9}, {%0,%1,%2,%3};"
        : "+f"(c[0]), "+f"(c[1]), "+f"(c[2]), "+f"(c[3])
        : "r"(a[0]), "r"(a[1]), "r"(a[2]), "r"(a[3]), "r"(b[0]), "r"(b[1]));
}
#define CP_ASYNC16(dst, src) \
    asm volatile("cp.async.cg.shared.global [%0], [%1], 16;" :: "r"(dst), "l"(src))
#define CP_COMMIT() asm volatile("cp.async.commit_group;" ::: "memory")
#define CP_WAIT1()  asm volatile("cp.async.wait_group 1;" ::: "memory")
#define CP_WAIT0()  asm volatile("cp.async.wait_group 0;" ::: "memory")

// ============================ tf32 mma GEMM body ============================
__device__ __forceinline__
void gemm_body(const float* __restrict__ A0, int lda0,
               const float* __restrict__ A1, int lda1,
               const float* __restrict__ Bw,
               const float* __restrict__ bias,
               const float* __restrict__ resid,
               const float* __restrict__ yv,
               float* __restrict__ C, int ldc,
               int K1, int Kw, int mode, int m0, int n0)
{
    extern __shared__ float sm[];
    float* As = sm;
    float* Bs = sm + 2 * 128 * PAD_;

    const int tid  = threadIdx.x;
    const int lane = tid & 31;
    const int wid  = tid >> 5;
    const int NC   = Kw >> 5;
    const int NC1  = K1 >> 5;

    const int lr = tid >> 3;
    const int lk = (tid & 7) * 4;

    const uint32_t aS0 = smem_u32(As);
    const uint32_t bS0 = smem_u32(Bs);

    auto prefetch = [&](int c, int s) {
        const float* Ap; int kb, lda;
        if (c < NC1) { Ap = A0; lda = lda0; kb = c * 32; }
        else         { Ap = A1; lda = lda1; kb = (c - NC1) * 32; }
        const uint32_t aT = aS0 + (uint32_t)(s * 128 * PAD_) * 4;
        const uint32_t bT = bS0 + (uint32_t)(s * 128 * PAD_) * 4;
        const float* srcB = Bw + (size_t)n0 * Kw + c * 32;
        #pragma unroll
        for (int it = 0; it < 4; ++it) {
            const int r = lr + it * 32;
            CP_ASYNC16(aT + (uint32_t)(r * PAD_ + lk) * 4,
                       Ap + (size_t)(m0 + r) * lda + kb + lk);
            CP_ASYNC16(bT + (uint32_t)(r * PAD_ + lk) * 4,
                       srcB + (size_t)r * Kw + lk);
        }
    };

    const int wm = (wid & 1) * 64;
    const int wn = (wid >> 1) * 32;

    float acc[4][4][4];
    #pragma unroll
    for (int i = 0; i < 4; ++i)
        #pragma unroll
        for (int j = 0; j < 4; ++j)
            #pragma unroll
            for (int r = 0; r < 4; ++r) acc[i][j][r] = 0.f;

    prefetch(0, 0);
    CP_COMMIT();

    for (int c = 0; c < NC; ++c) {
        const int s = c & 1;
        if (c + 1 < NC) { prefetch(c + 1, s ^ 1); CP_COMMIT(); CP_WAIT1(); }
        else            { CP_WAIT0(); }
        __syncthreads();

        const float* a_s = As + s * 128 * PAD_ + (wm + (lane >> 2)) * PAD_ + (lane & 3);
        const float* b_s = Bs + s * 128 * PAD_ + (wn + (lane >> 2)) * PAD_ + (lane & 3);

        #pragma unroll
        for (int ks = 0; ks < 4; ++ks) {
            const int k0 = ks * 8;
            uint32_t af[4][4];
            #pragma unroll
            for (int i = 0; i < 4; ++i) {
                const float* ap = a_s + i * 16 * PAD_ + k0;
                af[i][0] = f2tf(ap[0]);
                af[i][1] = f2tf(ap[8 * PAD_]);
                af[i][2] = f2tf(ap[4]);
                af[i][3] = f2tf(ap[8 * PAD_ + 4]);
            }
            #pragma unroll
            for (int j = 0; j < 4; ++j) {
                const float* bp = b_s + j * 8 * PAD_ + k0;
                uint32_t bf[2] = { f2tf(bp[0]), f2tf(bp[4]) };
                #pragma unroll
                for (int i = 0; i < 4; ++i) mma_tf32(acc[i][j], af[i], bf);
            }
        }
        __syncthreads();
    }

    const int row0 = m0 + wm + (lane >> 2);
    const int col0 = n0 + wn + (lane & 3) * 2;

    #pragma unroll
    for (int i = 0; i < 4; ++i) {
        #pragma unroll
        for (int half = 0; half < 2; ++half) {
            const int r = row0 + i * 16 + half * 8;
            float*       crow = C + (size_t)r * ldc;
            const float* rrow = resid ? resid + (size_t)r * ldc : nullptr;
            const float* yrow = yv    ? yv    + (size_t)r * ldc : nullptr;
            #pragma unroll
            for (int j = 0; j < 4; ++j) {
                const int cc = col0 + j * 8;
                float v0 = acc[i][j][half * 2 + 0];
                float v1 = acc[i][j][half * 2 + 1];
                if (mode == 0) {
                    *(float2*)(crow + cc) = make_float2(v0, v1);
                } else if (mode == 1) {
                    float2 bi = *(const float2*)(bias + cc);
                    float2 rv = *(const float2*)(rrow + cc);
                    float2 yw = *(const float2*)(yrow + cc);
                    float g0 = 1.f / (1.f + __expf(-(v0 + bi.x)));
                    float g1 = 1.f / (1.f + __expf(-(v1 + bi.y)));
                    *(float2*)(crow + cc) = make_float2(
                        g0 * rv.x + (1.f - g0) * yw.x,
                        g1 * rv.y + (1.f - g1) * yw.y);
                } else {
                    float2 bi = *(const float2*)(bias + cc);
                    float2 rv = *(const float2*)(rrow + cc);
                    *(float2*)(crow + cc) = make_float2(v0 + bi.x + rv.x,
                                                        v1 + bi.y + rv.y);
                }
            }
        }
    }
}

__global__ __launch_bounds__(256, 2)
void gemm_qkv(const float* __restrict__ A,
              const float* __restrict__ Wq, const float* __restrict__ Wk,
              const float* __restrict__ Wv,
              float* __restrict__ q, float* __restrict__ k, float* __restrict__ v)
{
    const int bx  = blockIdx.x;
    const int sel = bx % 3;
    const int m0  = (bx / 3) * 128;
    const float* Bw = (sel == 0) ? Wq : (sel == 1) ? Wk : Wv;
    float*       C  = (sel == 0) ? q  : (sel == 1) ? k  : v;
    gemm_body(A, 512, A, 512, Bw, nullptr, nullptr, nullptr, C, 128,
              512, 512, 0, m0, 0);
}

__global__ __launch_bounds__(256, 2)
void gemm_gen(const float* __restrict__ A0, int lda0,
              const float* __restrict__ A1, int lda1,
              const float* __restrict__ Bw,
              const float* __restrict__ bias,
              const float* __restrict__ resid,
              const float* __restrict__ yv,
              float* __restrict__ C, int K1, int Kw, int mode)
{
    const int bx = blockIdx.x;
    const int m0 = (bx >> 2) * 128;
    const int n0 = (bx & 3) * 128;
    gemm_body(A0, lda0, A1, lda1, Bw, bias, resid, yv, C, 512,
              K1, Kw, mode, m0, n0);
}

// ============================ prep kernels ==================================
__global__ void build_beff(const float* __restrict__ gW,
                           const float* __restrict__ V,
                           float* __restrict__ Beff)
{
    const int n = blockIdx.x;
    const int tid = threadIdx.x;
    ((float4*)(Beff + (size_t)n * 640))[tid] =
        ((const float4*)(gW + (size_t)n * 1024))[tid];
    const int h = tid >> 4, r = tid & 15;
    const float* w2 = gW + (size_t)n * 1024 + 512 + h * 64;
    const float* vr = V + (size_t)(h * 16 + r) * 64;
    float s = 0.f;
    #pragma unroll
    for (int d = 0; d < 64; ++d) s = fmaf(w2[d], vr[d], s);
    Beff[(size_t)n * 640 + 512 + tid] = s;
}

__global__ void build_rope(float* __restrict__ rc, float* __restrict__ rs)
{
    const int idx = blockIdx.x * 256 + threadIdx.x;
    const int pos = idx >> 5;
    const int ih  = idx & 31;
    const float theta = expf((float)ih * -0.28782313662425572f);
    float sn, cs;
    sincosf((float)pos * theta, &sn, &cs);
    rc[idx] = cs;  rs[idx] = sn;
}

// ============================ LayerNorm =====================================
__global__ void ln_kernel(const float* __restrict__ x,
                          const float* __restrict__ g,
                          const float* __restrict__ b,
                          float* __restrict__ out)
{
    const int n   = blockIdx.x;
    const int tid = threadIdx.x;
    const float* xr = x + (size_t)n * C_;

    float v0 = xr[tid];
    float v1 = xr[tid + 256];
    float s = v0 + v1;
    float q = v0 * v0 + v1 * v1;
    #pragma unroll
    for (int o = 16; o; o >>= 1) {
        s += __shfl_xor_sync(0xffffffffu, s, o);
        q += __shfl_xor_sync(0xffffffffu, q, o);
    }
    __shared__ float rs[8], rq[8];
    if ((tid & 31) == 0) { rs[tid >> 5] = s; rq[tid >> 5] = q; }
    __syncthreads();
    float st = 0.f, qt = 0.f;
    #pragma unroll
    for (int w = 0; w < 8; ++w) { st += rs[w]; qt += rq[w]; }

    const float mean = st * (1.f / 512.f);
    const float var  = qt * (1.f / 512.f) - mean * mean;
    const float rstd = rsqrtf(var + 1e-12f);

    float* orow = out + (size_t)n * C_;
    orow[tid]       = (v0 - mean) * rstd * g[tid]       + b[tid];
    orow[tid + 256] = (v1 - mean) * rstd * g[tid + 256] + b[tid + 256];
}

// ====================== rank->head expansion + RoPE (table) =================
__global__ void expand_rope_kernel(const float* __restrict__ ql,
                                   const float* __restrict__ kl,
                                   const float* __restrict__ U,
                                   const float* __restrict__ rc,
                                   const float* __restrict__ rs,
                                   float* __restrict__ q,
                                   float* __restrict__ k,
                                   int timeMode)
{
    const int n = blockIdx.x;
    const int tid = threadIdx.x;
    __shared__ float sq[128], sk[128];
    sq[tid] = ql[(size_t)n * RK_ + tid];
    sk[tid] = kl[(size_t)n * RK_ + tid];
    __syncthreads();

    const int pos = timeMode ? ((n >> 8) & 63) : (n & 255);

    #pragma unroll
    for (int pp = 0; pp < 2; ++pp) {
        const int p  = tid + pp * 128;
        const int h  = p >> 5;
        const int ih = p & 31;
        const float* Ue = U + (size_t)(h * 64 + 2 * ih) * 16;
        const float* Uo = Ue + 16;
        const float* sqh = sq + h * 16;
        const float* skh = sk + h * 16;

        float qe = 0.f, qo = 0.f, ke = 0.f, ko = 0.f;
        #pragma unroll
        for (int r = 0; r < 16; ++r) {
            const float ue = __ldg(Ue + r);
            const float uo = __ldg(Uo + r);
            qe = fmaf(ue, sqh[r], qe);  qo = fmaf(uo, sqh[r], qo);
            ke = fmaf(ue, skh[r], ke);  ko = fmaf(uo, skh[r], ko);
        }
        const float cs = __ldg(rc + pos * 32 + ih);
        const float sn = __ldg(rs + pos * 32 + ih);

        const size_t base = (size_t)n * C_ + h * 64 + 2 * ih;
        q[base]     = qe * cs - qo * sn;
        q[base + 1] = qe * sn + qo * cs;
        k[base]     = ke * cs - ko * sn;
        k[base + 1] = ke * sn + ko * cs;
    }
}

// ===================== mma.sync flash attention =============================
// 128 threads (4 warps). Block = one (sequence, head, 64-row q-tile).
// Warp w owns q-rows [16w, 16w+16). Scores via m16n8k8 tf32; softmax in
// registers (quad shuffles); P->A-frag via intra-quad shuffles; PV via mma.
template <int KV_TILES, bool TIME>
__global__ __launch_bounds__(128)
void attn_mma(const float* __restrict__ q, const float* __restrict__ k,
              const float* __restrict__ vlow, float* __restrict__ olow)
{
    __shared__ float qs[64 * 68];
    __shared__ float ks[64 * 68];
    __shared__ float vs[64 * 24];

    const int tid  = threadIdx.x;
    const int lane = tid & 31;
    const int w    = tid >> 5;
    const int head = blockIdx.y;

    int base, step;
    if (TIME) {
        const int b = blockIdx.x >> 8;
        const int l = blockIdx.x & 255;
        base = b * (T_ * L_) + l;  step = L_;
    } else {
        base = blockIdx.x * L_;    step = 1;
    }
    const int q0 = blockIdx.z * 64;

    // ---- load Q tile (scaled 1/sqrt(64)=0.125) ----
    #pragma unroll
    for (int p = 0; p < 8; ++p) {
        const int f = tid + p * 128;
        const int i = f >> 4;
        const int c = (f & 15) * 4;
        const int tok = base + (q0 + i) * step;
        float4 v = *(const float4*)(q + (size_t)tok * C_ + head * HD_ + c);
        v.x *= 0.125f; v.y *= 0.125f; v.z *= 0.125f; v.w *= 0.125f;
        *(float4*)&qs[i * 68 + c] = v;
    }

    const int qr = lane >> 2;        // quad row 0..7
    const int c  = lane & 3;         // quad col
    const int srcA = (lane & 28) | (c >> 1);
    const int srcB = srcA + 2;

    float m0v = -1e30f, m1v = -1e30f, l0v = 0.f, l1v = 0.f;
    float accO[2][4];
    #pragma unroll
    for (int nf = 0; nf < 2; ++nf)
        #pragma unroll
        for (int r = 0; r < 4; ++r) accO[nf][r] = 0.f;

    for (int kt = 0; kt < KV_TILES; ++kt) {
        // ---- load K tile + V tile ----
        #pragma unroll
        for (int p = 0; p < 8; ++p) {
            const int f = tid + p * 128;
            const int j = f >> 4;
            const int cc = (f & 15) * 4;
            const int tok = base + (kt * 64 + j) * step;
            *(float4*)&ks[j * 68 + cc] =
                *(const float4*)(k + (size_t)tok * C_ + head * HD_ + cc);
        }
        #pragma unroll
        for (int p = 0; p < 2; ++p) {
            const int f = tid + p * 128;
            const int j = f >> 2;
            const int rq = (f & 3) * 4;
            const int tok = base + (kt * 64 + j) * step;
            *(float4*)&vs[j * 24 + rq] =
                *(const float4*)(vlow + (size_t)tok * RK_ + head * 16 + rq);
        }
        __syncthreads();

        // ---- scores S[16 x 64] per warp via mma ----
        float s[8][4];
        #pragma unroll
        for (int j = 0; j < 8; ++j)
            #pragma unroll
            for (int r = 0; r < 4; ++r) s[j][r] = 0.f;

        const float* a_s = qs + (w * 16 + qr) * 68 + c;
        const float* b_s = ks + qr * 68 + c;
        #pragma unroll
        for (int ks8 = 0; ks8 < 8; ++ks8) {
            const int k0 = ks8 * 8;
            uint32_t af[4];
            const float* ap = a_s + k0;
            af[0] = f2tf(ap[0]);
            af[1] = f2tf(ap[8 * 68]);
            af[2] = f2tf(ap[4]);
            af[3] = f2tf(ap[8 * 68 + 4]);
            #pragma unroll
            for (int j = 0; j < 8; ++j) {
                const float* bp = b_s + j * 8 * 68 + k0;
                uint32_t bf[2] = { f2tf(bp[0]), f2tf(bp[4]) };
                mma_tf32(s[j], af, bf);
            }
        }

        // ---- online softmax (registers + quad shuffles) ----
        float tm0 = -1e30f, tm1 = -1e30f;
        #pragma unroll
        for (int j = 0; j < 8; ++j) {
            tm0 = fmaxf(tm0, fmaxf(s[j][0], s[j][1]));
            tm1 = fmaxf(tm1, fmaxf(s[j][2], s[j][3]));
        }
        tm0 = fmaxf(tm0, __shfl_xor_sync(0xffffffffu, tm0, 1));
        tm0 = fmaxf(tm0, __shfl_xor_sync(0xffffffffu, tm0, 2));
        tm1 = fmaxf(tm1, __shfl_xor_sync(0xffffffffu, tm1, 1));
        tm1 = fmaxf(tm1, __shfl_xor_sync(0xffffffffu, tm1, 2));

        const float mn0 = fmaxf(m0v, tm0);
        const float mn1 = fmaxf(m1v, tm1);
        const float al0 = __expf(m0v - mn0);
        const float al1 = __expf(m1v - mn1);
        m0v = mn0; m1v = mn1;

        float rs0 = 0.f, rs1 = 0.f;
        #pragma unroll
        for (int j = 0; j < 8; ++j) {
            s[j][0] = __expf(s[j][0] - mn0);
            s[j][1] = __expf(s[j][1] - mn0);
            s[j][2] = __expf(s[j][2] - mn1);
            s[j][3] = __expf(s[j][3] - mn1);
            rs0 += s[j][0] + s[j][1];
            rs1 += s[j][2] + s[j][3];
        }
        rs0 += __shfl_xor_sync(0xffffffffu, rs0, 1);
        rs0 += __shfl_xor_sync(0xffffffffu, rs0, 2);
        rs1 += __shfl_xor_sync(0xffffffffu, rs1, 1);
        rs1 += __shfl_xor_sync(0xffffffffu, rs1, 2);
        l0v = l0v * al0 + rs0;
        l1v = l1v * al1 + rs1;

        #pragma unroll
        for (int nf = 0; nf < 2; ++nf) {
            accO[nf][0] *= al0; accO[nf][1] *= al0;
            accO[nf][2] *= al1; accO[nf][3] *= al1;
        }

        // ---- PV: reshape P score-layout -> A-frag, mma with V ----
        #pragma unroll
        for (int j = 0; j < 8; ++j) {
            const float t0 = __shfl_sync(0xffffffffu, s[j][0], srcA);
            const float t1 = __shfl_sync(0xffffffffu, s[j][1], srcA);
            const float t2 = __shfl_sync(0xffffffffu, s[j][2], srcA);
            const float t3 = __shfl_sync(0xffffffffu, s[j][3], srcA);
            const float u0 = __shfl_sync(0xffffffffu, s[j][0], srcB);
            const float u1 = __shfl_sync(0xffffffffu, s[j][1], srcB);
            const float u2 = __shfl_sync(0xffffffffu, s[j][2], srcB);
            const float u3 = __shfl_sync(0xffffffffu, s[j][3], srcB);
            uint32_t pa[4];
            pa[0] = f2tf((c & 1) ? t1 : t0);
            pa[1] = f2tf((c & 1) ? t3 : t2);
            pa[2] = f2tf((c & 1) ? u1 : u0);
            pa[3] = f2tf((c & 1) ? u3 : u2);
            #pragma unroll
            for (int nf = 0; nf < 2; ++nf) {
                const float* vp = vs + (j * 8 + c) * 24 + nf * 8 + qr;
                uint32_t bf[2] = { f2tf(vp[0]), f2tf(vp[4 * 24]) };
                mma_tf32(accO[nf], pa, bf);
            }
        }
        __syncthreads();
    }

    // ---- epilogue: normalize, store olow ----
    const float inv0 = 1.f / l0v;
    const float inv1 = 1.f / l1v;
    const int r0 = q0 + w * 16 + qr;
    const int r1 = r0 + 8;
    const size_t tok0 = (size_t)(base + r0 * step) * RK_ + head * 16;
    const size_t tok1 = (size_t)(base + r1 * step) * RK_ + head * 16;
    #pragma unroll
    for (int nf = 0; nf < 2; ++nf) {
        const int col = nf * 8 + c * 2;
        *(float2*)(olow + tok0 + col) = make_float2(accO[nf][0] * inv0,
                                                    accO[nf][1] * inv0);
        *(float2*)(olow + tok1 + col) = make_float2(accO[nf][2] * inv1,
                                                    accO[nf][3] * inv1);
    }
}

// ============================ V projection (round-3, known good) ============
__global__ void vproj_kernel(const float* __restrict__ olow,
                             const float* __restrict__ V,
                             float* __restrict__ y)
{
    const int n = blockIdx.x;
    const int tid = threadIdx.x;
    __shared__ float so[128];
    so[tid] = olow[(size_t)n * RK_ + tid];
    __syncthreads();

    const int c0 = tid * 4;
    const int h  = c0 >> 6;
    const int d0 = c0 & 63;
    const float* oh = so + h * 16;

    float4 a = make_float4(0.f, 0.f, 0.f, 0.f);
    #pragma unroll
    for (int r = 0; r < 16; ++r) {
        const float ov = oh[r];
        float4 v4 = *(const float4*)(V + (size_t)((h * 16 + r) * 64 + d0));
        a.x = fmaf(ov, v4.x, a.x);
        a.y = fmaf(ov, v4.y, a.y);
        a.z = fmaf(ov, v4.z, a.z);
        a.w = fmaf(ov, v4.w, a.w);
    }
    *(float4*)(y + (size_t)n * C_ + c0) = a;
}

// ============================ launch ========================================
extern "C" void kernel_launch(void* const* d_in, const int* in_sizes, int n_in,
                              void* d_out, int out_size)
{
    const float* x    = (const float*)d_in[0];
    const float* tWq  = (const float*)d_in[3];
    const float* tWk  = (const float*)d_in[4];
    const float* tWv  = (const float*)d_in[5];
    const float* tU   = (const float*)d_in[6];
    const float* tV   = (const float*)d_in[7];
    const float* aWq  = (const float*)d_in[8];
    const float* aWk  = (const float*)d_in[9];
    const float* aWv  = (const float*)d_in[10];
    const float* aU   = (const float*)d_in[11];
    const float* aV   = (const float*)d_in[12];
    const float* ln1g = (const float*)d_in[13];
    const float* ln1b = (const float*)d_in[14];
    const float* ln2g = (const float*)d_in[15];
    const float* ln2b = (const float*)d_in[16];
    const float* ln3g = (const float*)d_in[17];
    const float* ln3b = (const float*)d_in[18];
    const float* projW= (const float*)d_in[19];
    const float* projb= (const float*)d_in[20];
    const float* gtW  = (const float*)d_in[21];
    const float* gtb  = (const float*)d_in[22];
    const float* gaW  = (const float*)d_in[23];
    const float* gab  = (const float*)d_in[24];
    float* out = (float*)d_out;

    float *xn, *qb, *kb, *yb, *x1, *x2, *qlo, *klo, *vlo, *olo;
    float *befft, *beffa, *ropec, *ropes;
    cudaGetSymbolAddress((void**)&xn,  g_xn);
    cudaGetSymbolAddress((void**)&qb,  g_q);
    cudaGetSymbolAddress((void**)&kb,  g_k);
    cudaGetSymbolAddress((void**)&yb,  g_y);
    cudaGetSymbolAddress((void**)&x1,  g_x1);
    cudaGetSymbolAddress((void**)&x2,  g_x2);
    cudaGetSymbolAddress((void**)&qlo, g_qlo);
    cudaGetSymbolAddress((void**)&klo, g_klo);
    cudaGetSymbolAddress((void**)&vlo, g_vlo);
    cudaGetSymbolAddress((void**)&olo, g_olo);
    cudaGetSymbolAddress((void**)&befft, g_befft);
    cudaGetSymbolAddress((void**)&beffa, g_beffa);
    cudaGetSymbolAddress((void**)&ropec, g_ropec);
    cudaGetSymbolAddress((void**)&ropes, g_ropes);

    static bool attr_set = false;
    if (!attr_set) {
        cudaFuncSetAttribute(gemm_qkv, cudaFuncAttributeMaxDynamicSharedMemorySize, GEMM_SMEM);
        cudaFuncSetAttribute(gemm_gen, cudaFuncAttributeMaxDynamicSharedMemorySize, GEMM_SMEM);
        attr_set = true;
    }

    // -------- prep --------
    build_rope<<<32, 256>>>(ropec, ropes);
    build_beff<<<512, 128>>>(gtW, tV, befft);
    build_beff<<<512, 128>>>(gaW, aV, beffa);

    // ---------------- stage A: time attention ----------------
    ln_kernel<<<N_, 256>>>(x, ln1g, ln1b, xn);
    gemm_qkv<<<3 * (N_ / 128), 256, GEMM_SMEM>>>(xn, tWq, tWk, tWv, qlo, klo, vlo);
    expand_rope_kernel<<<N_, 128>>>(qlo, klo, tU, ropec, ropes, qb, kb, 1);
    attn_mma<1, true><<<dim3(B_ * L_, 8, 1), 128>>>(qb, kb, vlo, olo);
    vproj_kernel<<<N_, 128>>>(olo, tV, yb);
    gemm_gen<<<4 * (N_ / 128), 256, GEMM_SMEM>>>(x, 512, olo, 128, befft, gtb, x, yb, x1, 512, 640, 1);

    // ---------------- stage B: residue attention ----------------
    ln_kernel<<<N_, 256>>>(x1, ln2g, ln2b, xn);
    gemm_qkv<<<3 * (N_ / 128), 256, GEMM_SMEM>>>(xn, aWq, aWk, aWv, qlo, klo, vlo);
    expand_rope_kernel<<<N_, 128>>>(qlo, klo, aU, ropec, ropes, qb, kb, 0);
    attn_mma<4, false><<<dim3(B_ * T_, 8, 4), 128>>>(qb, kb, vlo, olo);
    vproj_kernel<<<N_, 128>>>(olo, aV, yb);
    gemm_gen<<<4 * (N_ / 128), 256, GEMM_SMEM>>>(x1, 512, olo, 128, beffa, gab, x1, yb, x2, 512, 640, 1);

    // ---------------- stage C: output projection ----------------
    ln_kernel<<<N_, 256>>>(x2, ln3g, ln3b, xn);
    gemm_gen<<<4 * (N_ / 128), 256, GEMM_SMEM>>>(xn, 512, xn, 512, projW, projb, x2, nullptr, out, 512, 512, 2);
}

// round 7
// speedup vs baseline: 2.6080x; 2.0131x over previous
#include <cuda_runtime.h>
#include <cstdint>

// ============================================================================
// ProteinSpatioTemporalAttention — round 6 (resubmit; prior run died to a
// container-infra failure, not a kernel error):
//  - tf32 mma.sync GEMMs (cp.async), merged QKV, Beff gate (K=640)
//  - attention FUSES rank->head expansion + RoPE (reads qlo/klo directly;
//    expand_rope kernel and 256MB q/k buffers deleted)
// ============================================================================

namespace {
constexpr int B_  = 4;
constexpr int T_  = 64;
constexpr int L_  = 256;
constexpr int C_  = 512;
constexpr int RK_ = 128;
constexpr int N_  = B_ * T_ * L_;   // 65536 tokens

constexpr int PAD_ = 36;
constexpr int GEMM_SMEM = 2 * 2 * 128 * PAD_ * 4;   // 73728 bytes

// attention dynamic smem layout (floats)
constexpr int AT_QS  = 0;                 // 64*68
constexpr int AT_KS  = AT_QS + 64 * 68;   // 64*68
constexpr int AT_VS  = AT_KS + 64 * 68;   // 64*24
constexpr int AT_UT  = AT_VS + 64 * 24;   // 16*66
constexpr int AT_LOT = AT_UT + 16 * 66;   // 16*65
constexpr int AT_TOT = AT_LOT + 16 * 65;  // 12336 floats
constexpr int ATTN_SMEM = AT_TOT * 4;     // 49344 bytes
}

// -------------------- scratch (device globals; no cudaMalloc) ---------------
__device__ float g_xn [N_ * C_];
__device__ float g_y  [N_ * C_];
__device__ float g_x1 [N_ * C_];
__device__ float g_x2 [N_ * C_];
__device__ float g_qlo[N_ * RK_];
__device__ float g_klo[N_ * RK_];
__device__ float g_vlo[N_ * RK_];
__device__ float g_olo[N_ * RK_];
__device__ float g_befft[512 * 640];
__device__ float g_beffa[512 * 640];
__device__ float g_ropec[256 * 32];
__device__ float g_ropes[256 * 32];

// ============================ PTX helpers ===================================
__device__ __forceinline__ uint32_t smem_u32(const void* p) {
    uint32_t a;
    asm("{ .reg .u64 t; cvta.to.shared.u64 t, %1; cvt.u32.u64 %0, t; }"
        : "=r"(a) : "l"(p));
    return a;
}
__device__ __forceinline__ uint32_t f2tf(float x) {
    uint32_t r;
    asm("cvt.rna.tf32.f32 %0, %1;" : "=r"(r) : "f"(x));
    return r;
}
__device__ __forceinline__ void mma_tf32(float* c, const uint32_t* a, const uint32_t* b) {
    asm volatile("mma.sync.aligned.m16n8k8.row.col.f32.tf32.tf32.f32 "
        "{%0,%1,%2,%3}, {%4,%5,%6,%7}, {%8,%9}, {%0,%1,%2,%3};"
        : "+f"(c[0]), "+f"(c[1]), "+f"(c[2]), "+f"(c[3])
        : "r"(a[0]), "r"(a[1]), "r"(a[2]), "r"(a[3]), "r"(b[0]), "r"(b[1]));
}
#define CP_ASYNC16(dst, src) \
    asm volatile("cp.async.cg.shared.global [%0], [%1], 16;" :: "r"(dst), "l"(src))
#define CP_COMMIT() asm volatile("cp.async.commit_group;" ::: "memory")
#define CP_WAIT1()  asm volatile("cp.async.wait_group 1;" ::: "memory")
#define CP_WAIT0()  asm volatile("cp.async.wait_group 0;" ::: "memory")

// ============================ tf32 mma GEMM body ============================
__device__ __forceinline__
void gemm_body(const float* __restrict__ A0, int lda0,
               const float* __restrict__ A1, int lda1,
               const float* __restrict__ Bw,
               const float* __restrict__ bias,
               const float* __restrict__ resid,
               const float* __restrict__ yv,
               float* __restrict__ C, int ldc,
               int K1, int Kw, int mode, int m0, int n0)
{
    extern __shared__ float sm[];
    float* As = sm;
    float* Bs = sm + 2 * 128 * PAD_;

    const int tid  = threadIdx.x;
    const int lane = tid & 31;
    const int wid  = tid >> 5;
    const int NC   = Kw >> 5;
    const int NC1  = K1 >> 5;

    const int lr = tid >> 3;
    const int lk = (tid & 7) * 4;

    const uint32_t aS0 = smem_u32(As);
    const uint32_t bS0 = smem_u32(Bs);

    auto prefetch = [&](int c, int s) {
        const float* Ap; int kb, lda;
        if (c < NC1) { Ap = A0; lda = lda0; kb = c * 32; }
        else         { Ap = A1; lda = lda1; kb = (c - NC1) * 32; }
        const uint32_t aT = aS0 + (uint32_t)(s * 128 * PAD_) * 4;
        const uint32_t bT = bS0 + (uint32_t)(s * 128 * PAD_) * 4;
        const float* srcB = Bw + (size_t)n0 * Kw + c * 32;
        #pragma unroll
        for (int it = 0; it < 4; ++it) {
            const int r = lr + it * 32;
            CP_ASYNC16(aT + (uint32_t)(r * PAD_ + lk) * 4,
                       Ap + (size_t)(m0 + r) * lda + kb + lk);
            CP_ASYNC16(bT + (uint32_t)(r * PAD_ + lk) * 4,
                       srcB + (size_t)r * Kw + lk);
        }
    };

    const int wm = (wid & 1) * 64;
    const int wn = (wid >> 1) * 32;

    float acc[4][4][4];
    #pragma unroll
    for (int i = 0; i < 4; ++i)
        #pragma unroll
        for (int j = 0; j < 4; ++j)
            #pragma unroll
            for (int r = 0; r < 4; ++r) acc[i][j][r] = 0.f;

    prefetch(0, 0);
    CP_COMMIT();

    for (int c = 0; c < NC; ++c) {
        const int s = c & 1;
        if (c + 1 < NC) { prefetch(c + 1, s ^ 1); CP_COMMIT(); CP_WAIT1(); }
        else            { CP_WAIT0(); }
        __syncthreads();

        const float* a_s = As + s * 128 * PAD_ + (wm + (lane >> 2)) * PAD_ + (lane & 3);
        const float* b_s = Bs + s * 128 * PAD_ + (wn + (lane >> 2)) * PAD_ + (lane & 3);

        #pragma unroll
        for (int ks = 0; ks < 4; ++ks) {
            const int k0 = ks * 8;
            uint32_t af[4][4];
            #pragma unroll
            for (int i = 0; i < 4; ++i) {
                const float* ap = a_s + i * 16 * PAD_ + k0;
                af[i][0] = f2tf(ap[0]);
                af[i][1] = f2tf(ap[8 * PAD_]);
                af[i][2] = f2tf(ap[4]);
                af[i][3] = f2tf(ap[8 * PAD_ + 4]);
            }
            #pragma unroll
            for (int j = 0; j < 4; ++j) {
                const float* bp = b_s + j * 8 * PAD_ + k0;
                uint32_t bf[2] = { f2tf(bp[0]), f2tf(bp[4]) };
                #pragma unroll
                for (int i = 0; i < 4; ++i) mma_tf32(acc[i][j], af[i], bf);
            }
        }
        __syncthreads();
    }

    const int row0 = m0 + wm + (lane >> 2);
    const int col0 = n0 + wn + (lane & 3) * 2;

    #pragma unroll
    for (int i = 0; i < 4; ++i) {
        #pragma unroll
        for (int half = 0; half < 2; ++half) {
            const int r = row0 + i * 16 + half * 8;
            float*       crow = C + (size_t)r * ldc;
            const float* rrow = resid ? resid + (size_t)r * ldc : nullptr;
            const float* yrow = yv    ? yv    + (size_t)r * ldc : nullptr;
            #pragma unroll
            for (int j = 0; j < 4; ++j) {
                const int cc = col0 + j * 8;
                float v0 = acc[i][j][half * 2 + 0];
                float v1 = acc[i][j][half * 2 + 1];
                if (mode == 0) {
                    *(float2*)(crow + cc) = make_float2(v0, v1);
                } else if (mode == 1) {
                    float2 bi = *(const float2*)(bias + cc);
                    float2 rv = *(const float2*)(rrow + cc);
                    float2 yw = *(const float2*)(yrow + cc);
                    float g0 = 1.f / (1.f + __expf(-(v0 + bi.x)));
                    float g1 = 1.f / (1.f + __expf(-(v1 + bi.y)));
                    *(float2*)(crow + cc) = make_float2(
                        g0 * rv.x + (1.f - g0) * yw.x,
                        g1 * rv.y + (1.f - g1) * yw.y);
                } else {
                    float2 bi = *(const float2*)(bias + cc);
                    float2 rv = *(const float2*)(rrow + cc);
                    *(float2*)(crow + cc) = make_float2(v0 + bi.x + rv.x,
                                                        v1 + bi.y + rv.y);
                }
            }
        }
    }
}

__global__ __launch_bounds__(256, 2)
void gemm_qkv(const float* __restrict__ A,
              const float* __restrict__ Wq, const float* __restrict__ Wk,
              const float* __restrict__ Wv,
              float* __restrict__ q, float* __restrict__ k, float* __restrict__ v)
{
    const int bx  = blockIdx.x;
    const int sel = bx % 3;
    const int m0  = (bx / 3) * 128;
    const float* Bw = (sel == 0) ? Wq : (sel == 1) ? Wk : Wv;
    float*       C  = (sel == 0) ? q  : (sel == 1) ? k  : v;
    gemm_body(A, 512, A, 512, Bw, nullptr, nullptr, nullptr, C, 128,
              512, 512, 0, m0, 0);
}

__global__ __launch_bounds__(256, 2)
void gemm_gen(const float* __restrict__ A0, int lda0,
              const float* __restrict__ A1, int lda1,
              const float* __restrict__ Bw,
              const float* __restrict__ bias,
              const float* __restrict__ resid,
              const float* __restrict__ yv,
              float* __restrict__ C, int K1, int Kw, int mode)
{
    const int bx = blockIdx.x;
    const int m0 = (bx >> 2) * 128;
    const int n0 = (bx & 3) * 128;
    gemm_body(A0, lda0, A1, lda1, Bw, bias, resid, yv, C, 512,
              K1, Kw, mode, m0, n0);
}

// ============================ prep kernels ==================================
__global__ void build_beff(const float* __restrict__ gW,
                           const float* __restrict__ V,
                           float* __restrict__ Beff)
{
    const int n = blockIdx.x;
    const int tid = threadIdx.x;
    ((float4*)(Beff + (size_t)n * 640))[tid] =
        ((const float4*)(gW + (size_t)n * 1024))[tid];
    const int h = tid >> 4, r = tid & 15;
    const float* w2 = gW + (size_t)n * 1024 + 512 + h * 64;
    const float* vr = V + (size_t)(h * 16 + r) * 64;
    float s = 0.f;
    #pragma unroll
    for (int d = 0; d < 64; ++d) s = fmaf(w2[d], vr[d], s);
    Beff[(size_t)n * 640 + 512 + tid] = s;
}

__global__ void build_rope(float* __restrict__ rc, float* __restrict__ rs)
{
    const int idx = blockIdx.x * 256 + threadIdx.x;
    const int pos = idx >> 5;
    const int ih  = idx & 31;
    const float theta = expf((float)ih * -0.28782313662425572f);
    float sn, cs;
    sincosf((float)pos * theta, &sn, &cs);
    rc[idx] = cs;  rs[idx] = sn;
}

// ============================ LayerNorm =====================================
__global__ void ln_kernel(const float* __restrict__ x,
                          const float* __restrict__ g,
                          const float* __restrict__ b,
                          float* __restrict__ out)
{
    const int n   = blockIdx.x;
    const int tid = threadIdx.x;
    const float* xr = x + (size_t)n * C_;

    float v0 = xr[tid];
    float v1 = xr[tid + 256];
    float s = v0 + v1;
    float q = v0 * v0 + v1 * v1;
    #pragma unroll
    for (int o = 16; o; o >>= 1) {
        s += __shfl_xor_sync(0xffffffffu, s, o);
        q += __shfl_xor_sync(0xffffffffu, q, o);
    }
    __shared__ float rs[8], rq[8];
    if ((tid & 31) == 0) { rs[tid >> 5] = s; rq[tid >> 5] = q; }
    __syncthreads();
    float st = 0.f, qt = 0.f;
    #pragma unroll
    for (int w = 0; w < 8; ++w) { st += rs[w]; qt += rq[w]; }

    const float mean = st * (1.f / 512.f);
    const float var  = qt * (1.f / 512.f) - mean * mean;
    const float rstd = rsqrtf(var + 1e-12f);

    float* orow = out + (size_t)n * C_;
    orow[tid]       = (v0 - mean) * rstd * g[tid]       + b[tid];
    orow[tid + 256] = (v1 - mean) * rstd * g[tid + 256] + b[tid + 256];
}

// ===================== fused mma flash attention ============================
// 128 threads (4 warps). Block = (sequence, head, 64-row q-tile).
// Expands q/k from rank space (U[h]) + RoPE inside the kernel.
template <int KV_TILES, bool TIME>
__global__ __launch_bounds__(128)
void attn_fused(const float* __restrict__ qlo, const float* __restrict__ klo,
                const float* __restrict__ vlow, const float* __restrict__ U,
                const float* __restrict__ rc, const float* __restrict__ rs,
                float* __restrict__ olow)
{
    extern __shared__ float sm[];
    float* qs  = sm + AT_QS;    // [64][68]
    float* ks  = sm + AT_KS;    // [64][68]
    float* vs  = sm + AT_VS;    // [64][24]
    float* Ut  = sm + AT_UT;    // [16][66]  U transposed [r][d]
    float* lot = sm + AT_LOT;   // [16][65]  low-rank tile transposed [r][i]

    const int tid  = threadIdx.x;
    const int lane = tid & 31;
    const int w    = tid >> 5;
    const int head = blockIdx.y;

    int base, step;
    if (TIME) {
        const int b = blockIdx.x >> 8;
        const int l = blockIdx.x & 255;
        base = b * (T_ * L_) + l;  step = L_;
    } else {
        base = blockIdx.x * L_;    step = 1;
    }
    const int q0 = blockIdx.z * 64;

    const int ei   = tid >> 1;       // expansion row 0..63
    const int ehalf= tid & 1;        // 16-pair half

    // ---- load U[h] transposed ----
    #pragma unroll
    for (int p = 0; p < 2; ++p) {
        const int idx = tid + p * 128;
        const int d = idx >> 2, r4 = (idx & 3) * 4;
        float4 u = *(const float4*)(U + ((size_t)head * 64 + d) * 16 + r4);
        Ut[(r4 + 0) * 66 + d] = u.x;
        Ut[(r4 + 1) * 66 + d] = u.y;
        Ut[(r4 + 2) * 66 + d] = u.z;
        Ut[(r4 + 3) * 66 + d] = u.w;
    }
    // ---- load qlo tile transposed ----
    #pragma unroll
    for (int p = 0; p < 2; ++p) {
        const int idx = tid + p * 128;
        const int i = idx >> 2, r4 = (idx & 3) * 4;
        const int tok = base + (q0 + i) * step;
        float4 v = *(const float4*)(qlo + (size_t)tok * RK_ + head * 16 + r4);
        lot[(r4 + 0) * 65 + i] = v.x;
        lot[(r4 + 1) * 65 + i] = v.y;
        lot[(r4 + 2) * 65 + i] = v.z;
        lot[(r4 + 3) * 65 + i] = v.w;
    }
    __syncthreads();

    // ---- expand Q + RoPE + scale ----
    {
        float qe[16], qo[16];
        #pragma unroll
        for (int pp = 0; pp < 16; ++pp) { qe[pp] = 0.f; qo[pp] = 0.f; }
        #pragma unroll
        for (int r = 0; r < 16; ++r) {
            const float lv = lot[r * 65 + ei];
            const float* ur = Ut + r * 66 + ehalf * 32;
            #pragma unroll
            for (int pp = 0; pp < 16; ++pp) {
                qe[pp] = fmaf(ur[2 * pp],     lv, qe[pp]);
                qo[pp] = fmaf(ur[2 * pp + 1], lv, qo[pp]);
            }
        }
        const int pos = q0 + ei;
        #pragma unroll
        for (int pp = 0; pp < 16; ++pp) {
            const int ih = ehalf * 16 + pp;
            const float cs = __ldg(rc + pos * 32 + ih);
            const float sn = __ldg(rs + pos * 32 + ih);
            qs[ei * 68 + 2 * ih]     = (qe[pp] * cs - qo[pp] * sn) * 0.125f;
            qs[ei * 68 + 2 * ih + 1] = (qe[pp] * sn + qo[pp] * cs) * 0.125f;
        }
    }
    __syncthreads();

    const int qr = lane >> 2;
    const int c  = lane & 3;
    const int srcA = (lane & 28) | (c >> 1);
    const int srcB = srcA + 2;

    float m0v = -1e30f, m1v = -1e30f, l0v = 0.f, l1v = 0.f;
    float accO[2][4];
    #pragma unroll
    for (int nf = 0; nf < 2; ++nf)
        #pragma unroll
        for (int r = 0; r < 4; ++r) accO[nf][r] = 0.f;

    for (int kt = 0; kt < KV_TILES; ++kt) {
        // ---- load klo tile (transposed) + V tile ----
        #pragma unroll
        for (int p = 0; p < 2; ++p) {
            const int idx = tid + p * 128;
            const int i = idx >> 2, r4 = (idx & 3) * 4;
            const int tok = base + (kt * 64 + i) * step;
            float4 v = *(const float4*)(klo + (size_t)tok * RK_ + head * 16 + r4);
            lot[(r4 + 0) * 65 + i] = v.x;
            lot[(r4 + 1) * 65 + i] = v.y;
            lot[(r4 + 2) * 65 + i] = v.z;
            lot[(r4 + 3) * 65 + i] = v.w;
        }
        #pragma unroll
        for (int p = 0; p < 2; ++p) {
            const int f = tid + p * 128;
            const int j = f >> 2;
            const int rq = (f & 3) * 4;
            const int tok = base + (kt * 64 + j) * step;
            *(float4*)&vs[j * 24 + rq] =
                *(const float4*)(vlow + (size_t)tok * RK_ + head * 16 + rq);
        }
        __syncthreads();

        // ---- expand K + RoPE ----
        {
            float ke[16], ko[16];
            #pragma unroll
            for (int pp = 0; pp < 16; ++pp) { ke[pp] = 0.f; ko[pp] = 0.f; }
            #pragma unroll
            for (int r = 0; r < 16; ++r) {
                const float lv = lot[r * 65 + ei];
                const float* ur = Ut + r * 66 + ehalf * 32;
                #pragma unroll
                for (int pp = 0; pp < 16; ++pp) {
                    ke[pp] = fmaf(ur[2 * pp],     lv, ke[pp]);
                    ko[pp] = fmaf(ur[2 * pp + 1], lv, ko[pp]);
                }
            }
            const int pos = kt * 64 + ei;
            #pragma unroll
            for (int pp = 0; pp < 16; ++pp) {
                const int ih = ehalf * 16 + pp;
                const float cs = __ldg(rc + pos * 32 + ih);
                const float sn = __ldg(rs + pos * 32 + ih);
                ks[ei * 68 + 2 * ih]     = ke[pp] * cs - ko[pp] * sn;
                ks[ei * 68 + 2 * ih + 1] = ke[pp] * sn + ko[pp] * cs;
            }
        }
        __syncthreads();

        // ---- scores S[16 x 64] per warp via mma ----
        float s[8][4];
        #pragma unroll
        for (int j = 0; j < 8; ++j)
            #pragma unroll
            for (int r = 0; r < 4; ++r) s[j][r] = 0.f;

        const float* a_s = qs + (w * 16 + qr) * 68 + c;
        const float* b_s = ks + qr * 68 + c;
        #pragma unroll
        for (int ks8 = 0; ks8 < 8; ++ks8) {
            const int k0 = ks8 * 8;
            uint32_t af[4];
            const float* ap = a_s + k0;
            af[0] = f2tf(ap[0]);
            af[1] = f2tf(ap[8 * 68]);
            af[2] = f2tf(ap[4]);
            af[3] = f2tf(ap[8 * 68 + 4]);
            #pragma unroll
            for (int j = 0; j < 8; ++j) {
                const float* bp = b_s + j * 8 * 68 + k0;
                uint32_t bf[2] = { f2tf(bp[0]), f2tf(bp[4]) };
                mma_tf32(s[j], af, bf);
            }
        }

        // ---- online softmax (registers + quad shuffles) ----
        float tm0 = -1e30f, tm1 = -1e30f;
        #pragma unroll
        for (int j = 0; j < 8; ++j) {
            tm0 = fmaxf(tm0, fmaxf(s[j][0], s[j][1]));
            tm1 = fmaxf(tm1, fmaxf(s[j][2], s[j][3]));
        }
        tm0 = fmaxf(tm0, __shfl_xor_sync(0xffffffffu, tm0, 1));
        tm0 = fmaxf(tm0, __shfl_xor_sync(0xffffffffu, tm0, 2));
        tm1 = fmaxf(tm1, __shfl_xor_sync(0xffffffffu, tm1, 1));
        tm1 = fmaxf(tm1, __shfl_xor_sync(0xffffffffu, tm1, 2));

        const float mn0 = fmaxf(m0v, tm0);
        const float mn1 = fmaxf(m1v, tm1);
        const float al0 = __expf(m0v - mn0);
        const float al1 = __expf(m1v - mn1);
        m0v = mn0; m1v = mn1;

        float rs0 = 0.f, rs1 = 0.f;
        #pragma unroll
        for (int j = 0; j < 8; ++j) {
            s[j][0] = __expf(s[j][0] - mn0);
            s[j][1] = __expf(s[j][1] - mn0);
            s[j][2] = __expf(s[j][2] - mn1);
            s[j][3] = __expf(s[j][3] - mn1);
            rs0 += s[j][0] + s[j][1];
            rs1 += s[j][2] + s[j][3];
        }
        rs0 += __shfl_xor_sync(0xffffffffu, rs0, 1);
        rs0 += __shfl_xor_sync(0xffffffffu, rs0, 2);
        rs1 += __shfl_xor_sync(0xffffffffu, rs1, 1);
        rs1 += __shfl_xor_sync(0xffffffffu, rs1, 2);
        l0v = l0v * al0 + rs0;
        l1v = l1v * al1 + rs1;

        #pragma unroll
        for (int nf = 0; nf < 2; ++nf) {
            accO[nf][0] *= al0; accO[nf][1] *= al0;
            accO[nf][2] *= al1; accO[nf][3] *= al1;
        }

        // ---- PV ----
        #pragma unroll
        for (int j = 0; j < 8; ++j) {
            const float t0 = __shfl_sync(0xffffffffu, s[j][0], srcA);
            const float t1 = __shfl_sync(0xffffffffu, s[j][1], srcA);
            const float t2 = __shfl_sync(0xffffffffu, s[j][2], srcA);
            const float t3 = __shfl_sync(0xffffffffu, s[j][3], srcA);
            const float u0 = __shfl_sync(0xffffffffu, s[j][0], srcB);
            const float u1 = __shfl_sync(0xffffffffu, s[j][1], srcB);
            const float u2 = __shfl_sync(0xffffffffu, s[j][2], srcB);
            const float u3 = __shfl_sync(0xffffffffu, s[j][3], srcB);
            uint32_t pa[4];
            pa[0] = f2tf((c & 1) ? t1 : t0);
            pa[1] = f2tf((c & 1) ? t3 : t2);
            pa[2] = f2tf((c & 1) ? u1 : u0);
            pa[3] = f2tf((c & 1) ? u3 : u2);
            #pragma unroll
            for (int nf = 0; nf < 2; ++nf) {
                const float* vp = vs + (j * 8 + c) * 24 + nf * 8 + qr;
                uint32_t bf[2] = { f2tf(vp[0]), f2tf(vp[4 * 24]) };
                mma_tf32(accO[nf], pa, bf);
            }
        }
        __syncthreads();
    }

    // ---- epilogue ----
    const float inv0 = 1.f / l0v;
    const float inv1 = 1.f / l1v;
    const int r0 = q0 + w * 16 + qr;
    const int r1 = r0 + 8;
    const size_t tok0 = (size_t)(base + r0 * step) * RK_ + head * 16;
    const size_t tok1 = (size_t)(base + r1 * step) * RK_ + head * 16;
    #pragma unroll
    for (int nf = 0; nf < 2; ++nf) {
        const int col = nf * 8 + c * 2;
        *(float2*)(olow + tok0 + col) = make_float2(accO[nf][0] * inv0,
                                                    accO[nf][1] * inv0);
        *(float2*)(olow + tok1 + col) = make_float2(accO[nf][2] * inv1,
                                                    accO[nf][3] * inv1);
    }
}

// ============================ V projection ==================================
__global__ void vproj_kernel(const float* __restrict__ olow,
                             const float* __restrict__ V,
                             float* __restrict__ y)
{
    const int n = blockIdx.x;
    const int tid = threadIdx.x;
    __shared__ float so[128];
    so[tid] = olow[(size_t)n * RK_ + tid];
    __syncthreads();

    const int c0 = tid * 4;
    const int h  = c0 >> 6;
    const int d0 = c0 & 63;
    const float* oh = so + h * 16;

    float4 a = make_float4(0.f, 0.f, 0.f, 0.f);
    #pragma unroll
    for (int r = 0; r < 16; ++r) {
        const float ov = oh[r];
        float4 v4 = *(const float4*)(V + (size_t)((h * 16 + r) * 64 + d0));
        a.x = fmaf(ov, v4.x, a.x);
        a.y = fmaf(ov, v4.y, a.y);
        a.z = fmaf(ov, v4.z, a.z);
        a.w = fmaf(ov, v4.w, a.w);
    }
    *(float4*)(y + (size_t)n * C_ + c0) = a;
}

// ============================ launch ========================================
extern "C" void kernel_launch(void* const* d_in, const int* in_sizes, int n_in,
                              void* d_out, int out_size)
{
    const float* x    = (const float*)d_in[0];
    const float* tWq  = (const float*)d_in[3];
    const float* tWk  = (const float*)d_in[4];
    const float* tWv  = (const float*)d_in[5];
    const float* tU   = (const float*)d_in[6];
    const float* tV   = (const float*)d_in[7];
    const float* aWq  = (const float*)d_in[8];
    const float* aWk  = (const float*)d_in[9];
    const float* aWv  = (const float*)d_in[10];
    const float* aU   = (const float*)d_in[11];
    const float* aV   = (const float*)d_in[12];
    const float* ln1g = (const float*)d_in[13];
    const float* ln1b = (const float*)d_in[14];
    const float* ln2g = (const float*)d_in[15];
    const float* ln2b = (const float*)d_in[16];
    const float* ln3g = (const float*)d_in[17];
    const float* ln3b = (const float*)d_in[18];
    const float* projW= (const float*)d_in[19];
    const float* projb= (const float*)d_in[20];
    const float* gtW  = (const float*)d_in[21];
    const float* gtb  = (const float*)d_in[22];
    const float* gaW  = (const float*)d_in[23];
    const float* gab  = (const float*)d_in[24];
    float* out = (float*)d_out;

    float *xn, *yb, *x1, *x2, *qlo, *klo, *vlo, *olo;
    float *befft, *beffa, *ropec, *ropes;
    cudaGetSymbolAddress((void**)&xn,  g_xn);
    cudaGetSymbolAddress((void**)&yb,  g_y);
    cudaGetSymbolAddress((void**)&x1,  g_x1);
    cudaGetSymbolAddress((void**)&x2,  g_x2);
    cudaGetSymbolAddress((void**)&qlo, g_qlo);
    cudaGetSymbolAddress((void**)&klo, g_klo);
    cudaGetSymbolAddress((void**)&vlo, g_vlo);
    cudaGetSymbolAddress((void**)&olo, g_olo);
    cudaGetSymbolAddress((void**)&befft, g_befft);
    cudaGetSymbolAddress((void**)&beffa, g_beffa);
    cudaGetSymbolAddress((void**)&ropec, g_ropec);
    cudaGetSymbolAddress((void**)&ropes, g_ropes);

    static bool attr_set = false;
    if (!attr_set) {
        cudaFuncSetAttribute(gemm_qkv, cudaFuncAttributeMaxDynamicSharedMemorySize, GEMM_SMEM);
        cudaFuncSetAttribute(gemm_gen, cudaFuncAttributeMaxDynamicSharedMemorySize, GEMM_SMEM);
        cudaFuncSetAttribute(attn_fused<1, true>,  cudaFuncAttributeMaxDynamicSharedMemorySize, ATTN_SMEM);
        cudaFuncSetAttribute(attn_fused<4, false>, cudaFuncAttributeMaxDynamicSharedMemorySize, ATTN_SMEM);
        attr_set = true;
    }

    // -------- prep --------
    build_rope<<<32, 256>>>(ropec, ropes);
    build_beff<<<512, 128>>>(gtW, tV, befft);
    build_beff<<<512, 128>>>(gaW, aV, beffa);

    // ---------------- stage A: time attention ----------------
    ln_kernel<<<N_, 256>>>(x, ln1g, ln1b, xn);
    gemm_qkv<<<3 * (N_ / 128), 256, GEMM_SMEM>>>(xn, tWq, tWk, tWv, qlo, klo, vlo);
    attn_fused<1, true><<<dim3(B_ * L_, 8, 1), 128, ATTN_SMEM>>>(qlo, klo, vlo, tU, ropec, ropes, olo);
    vproj_kernel<<<N_, 128>>>(olo, tV, yb);
    gemm_gen<<<4 * (N_ / 128), 256, GEMM_SMEM>>>(x, 512, olo, 128, befft, gtb, x, yb, x1, 512, 640, 1);

    // ---------------- stage B: residue attention ----------------
    ln_kernel<<<N_, 256>>>(x1, ln2g, ln2b, xn);
    gemm_qkv<<<3 * (N_ / 128), 256, GEMM_SMEM>>>(xn, aWq, aWk, aWv, qlo, klo, vlo);
    attn_fused<4, false><<<dim3(B_ * T_, 8, 4), 128, ATTN_SMEM>>>(qlo, klo, vlo, aU, ropec, ropes, olo);
    vproj_kernel<<<N_, 128>>>(olo, aV, yb);
    gemm_gen<<<4 * (N_ / 128), 256, GEMM_SMEM>>>(x1, 512, olo, 128, beffa, gab, x1, yb, x2, 512, 640, 1);

    // ---------------- stage C: output projection ----------------
    ln_kernel<<<N_, 256>>>(x2, ln3g, ln3b, xn);
    gemm_gen<<<4 * (N_ / 128), 256, GEMM_SMEM>>>(xn, 512, xn, 512, projW, projb, x2, nullptr, out, 512, 512, 2);
}